// round 2
// baseline (speedup 1.0000x reference)
#include <cuda_runtime.h>
#include <cstdint>

// out[r][c] = in[(2r+1)*N + (2c+1)],  N=8192, out is 4096x4096.
// Vectorized: one float4 load covers input cols 4c..4c+3 of an odd row;
// .y and .w are the odd columns -> one float2 store.

__global__ void downsample_odd_kernel(const float* __restrict__ in,
                                      float2* __restrict__ out,
                                      int n_out_rows,   // 4096
                                      int pairs_per_row // 2048 (float2 per out row)
                                      ) {
    long long idx = (long long)blockIdx.x * blockDim.x + threadIdx.x;
    long long total = (long long)n_out_rows * pairs_per_row;
    if (idx >= total) return;

    int r  = (int)(idx >> 11);        // pairs_per_row = 2048 = 2^11
    int c2 = (int)(idx & 2047);       // which float2 within the row

    const int N = 8192;
    // input row 2r+1, starting input column 4*c2 (aligned float4)
    const float4* src = reinterpret_cast<const float4*>(
        in + (long long)(2 * r + 1) * N) + c2;
    float4 v = *src;

    // output row r, float2 index c2
    out[(long long)r * pairs_per_row + c2] = make_float2(v.y, v.w);
}

extern "C" void kernel_launch(void* const* d_in, const int* in_sizes, int n_in,
                              void* d_out, int out_size) {
    const float* in = (const float*)d_in[0];
    float2* out = (float2*)d_out;

    const int n_out_rows = 4096;
    const int pairs_per_row = 2048;
    long long total = (long long)n_out_rows * pairs_per_row; // 8,388,608

    int threads = 256;
    int blocks = (int)((total + threads - 1) / threads);     // 32768
    downsample_odd_kernel<<<blocks, threads>>>(in, out, n_out_rows, pairs_per_row);
}

// round 6
// speedup vs baseline: 1.1331x; 1.1331x over previous
#include <cuda_runtime.h>
#include <cstdint>

// out[r][c] = in[(2r+1)*8192 + (2c+1)], out is 4096x4096 f32.
//
// Each thread handles 4 float4 input loads from one odd row, strided by
// 512 float4 across the row so every LDG.128 is fully warp-coalesced
// (32 consecutive threads -> 512B contiguous). All 4 loads are issued
// before any store (MLP=4). Each float4 yields 2 odd-column values ->
// one float2 store, also coalesced.

__global__ void downsample_odd_mlp4(const float4* __restrict__ in,
                                    float2* __restrict__ out) {
    // 512 threads per output row, 4096 rows -> 2,097,152 threads total
    int idx = blockIdx.x * blockDim.x + threadIdx.x;
    int r = idx >> 9;          // output row
    int g = idx & 511;         // lane group within row

    // input row 2r+1 as float4: 2048 float4 per row
    const float4* src = in + (long long)(2 * r + 1) * 2048;
    // output row r as float2: 2048 float2 per row
    float2* dst = out + (long long)r * 2048;

    // four independent loads, front-batched
    float4 a = src[g];
    float4 b = src[g + 512];
    float4 c = src[g + 1024];
    float4 d = src[g + 1536];

    dst[g]        = make_float2(a.y, a.w);
    dst[g + 512]  = make_float2(b.y, b.w);
    dst[g + 1024] = make_float2(c.y, c.w);
    dst[g + 1536] = make_float2(d.y, d.w);
}

extern "C" void kernel_launch(void* const* d_in, const int* in_sizes, int n_in,
                              void* d_out, int out_size) {
    const float4* in = (const float4*)d_in[0];
    float2* out = (float2*)d_out;

    const long long total = 4096LL * 512;   // 2,097,152 threads
    int threads = 256;
    int blocks = (int)(total / threads);    // 8192
    downsample_odd_mlp4<<<blocks, threads>>>(in, out);
}

// round 7
// speedup vs baseline: 1.1463x; 1.0117x over previous
#include <cuda_runtime.h>
#include <cstdint>

// out[r][c] = in[(2r+1)*8192 + (2c+1)], out is 4096x4096 f32.
//
// MLP=8: each thread issues 8 independent, fully warp-coalesced float4
// loads (stride 256 float4 across one odd input row) before any store.
// Each float4 yields 2 odd-column values -> one float2 store.
// Streaming cache hints (ldcs/stcs): zero reuse, evict-first.

__global__ void downsample_odd_mlp8(const float4* __restrict__ in,
                                    float2* __restrict__ out) {
    // 256 threads per output row, 4096 rows -> 1,048,576 threads
    int idx = blockIdx.x * blockDim.x + threadIdx.x;
    int r = idx >> 8;          // output row
    int g = idx & 255;         // group within row

    // input row 2r+1: 2048 float4 per row
    const float4* src = in + (long long)(2 * r + 1) * 2048;
    // output row r: 2048 float2 per row
    float2* dst = out + (long long)r * 2048;

    // eight independent loads, front-batched
    float4 v0 = __ldcs(src + g);
    float4 v1 = __ldcs(src + g + 256);
    float4 v2 = __ldcs(src + g + 512);
    float4 v3 = __ldcs(src + g + 768);
    float4 v4 = __ldcs(src + g + 1024);
    float4 v5 = __ldcs(src + g + 1280);
    float4 v6 = __ldcs(src + g + 1536);
    float4 v7 = __ldcs(src + g + 1792);

    __stcs(dst + g,        make_float2(v0.y, v0.w));
    __stcs(dst + g + 256,  make_float2(v1.y, v1.w));
    __stcs(dst + g + 512,  make_float2(v2.y, v2.w));
    __stcs(dst + g + 768,  make_float2(v3.y, v3.w));
    __stcs(dst + g + 1024, make_float2(v4.y, v4.w));
    __stcs(dst + g + 1280, make_float2(v5.y, v5.w));
    __stcs(dst + g + 1536, make_float2(v6.y, v6.w));
    __stcs(dst + g + 1792, make_float2(v7.y, v7.w));
}

extern "C" void kernel_launch(void* const* d_in, const int* in_sizes, int n_in,
                              void* d_out, int out_size) {
    const float4* in = (const float4*)d_in[0];
    float2* out = (float2*)d_out;

    const long long total = 4096LL * 256;   // 1,048,576 threads
    int threads = 256;
    int blocks = (int)(total / threads);    // 4096
    downsample_odd_mlp8<<<blocks, threads>>>(in, out);
}